// round 16
// baseline (speedup 1.0000x reference)
#include <cuda_runtime.h>
#include <cuda_bf16.h>
#include <math.h>

#define SUBN 20
#define KLEN 100
#define NE_MAX 500
#define T_MAX 100000

#define TT 128                // timesteps per synE block
#define GUARD 128
#define TP (T_MAX + 2*GUARD)  // g_synT row stride (100256)
#define CT 224                // conv tile timesteps (7 outputs/lane -> 1 wave)
#define CTH 640               // conv threads = 20 warps
#define OPL 7                 // outputs per lane (coprime with 32)
#define XROW 324              // xs row stride = CT+100 (mult of 4)
#define KROW 104              // kernel smem row stride
#define FROW 21               // filt smem row stride (odd -> conflict-free)

// ---------------- device scratch (zero-initialized; guards never written) ----
__device__ __align__(16) float g_synT[SUBN * TP];        // [s][t] + guard bands
__device__ __align__(16) float g_ekern2_sj[SUBN * KROW]; // 2*e_kern, [s][j]
__device__ float g_cw1[SUBN], g_cw2[SUBN];
__device__ float g_theta[SUBN], g_wplex2[SUBN];
__device__ float g_spk[KLEN];

__device__ __forceinline__ float tanh_fast(float x) {
    float y;
    asm("tanh.approx.f32 %0, %1;" : "=f"(y) : "f"(x));
    return y;
}

// ---------------- kernel A: prep (block 0) + syn_e scatter (transposed out) --
// (byte-identical to the golden kernel)
__global__ void __launch_bounds__(256) synE_kernel(
    const float* __restrict__ Se, const float* __restrict__ Cse,
    const float* __restrict__ Wsyn, const float* __restrict__ Tausyn,
    const float* __restrict__ Dsyn, const float* __restrict__ Wplex,
    const float* __restrict__ Wsub, const float* __restrict__ Wspk,
    const float* __restrict__ Tauspk, const float* __restrict__ Theta,
    const float* __restrict__ Cden, float* __restrict__ out_filters,
    int T, int nE)
{
    __shared__ float bins[TT][SUBN];
    __shared__ int   sidx[NE_MAX];
    __shared__ float sw[NE_MAX];
    int tid = threadIdx.x;

    if (blockIdx.x == 0) {
        for (int i = tid; i < SUBN * KLEN; i += 256) {
            int s = i / KLEN, k = i % KLEN;
            float te = fmaxf((float)k - Dsyn[s * 2 + 0], 0.f);
            float ti = fmaxf((float)k - Dsyn[s * 2 + 1], 0.f);
            float taue = Tausyn[s * 2 + 0];
            float taui = Tausyn[s * 2 + 1];
            float tte = te / (taue * taue);
            float tti = ti / (taui * taui);
            float ek = tte * expf(-tte) * Wsyn[s * 2 + 0];
            float ik = tti * expf(-tti) * Wsyn[s * 2 + 1];
            out_filters[s * KLEN + k] = ek;
            out_filters[(SUBN + s) * KLEN + k] = ik;
            g_ekern2_sj[s * KROW + k] = 2.f * ek;   // fold filt_e + filt_e
        }
        for (int i = tid; i < KLEN; i += 256) {
            float ts = Tauspk[0];
            float tt = (float)i / (ts * ts);
            g_spk[i] = tt * expf(-tt) * Wspk[0] * Wspk[0];
        }
        if (tid < SUBN) {
            int c1 = 2 * tid + 1, c2 = 2 * tid + 2;   // binary dendritic tree
            float w1 = (c1 < SUBN) ? Wsub[c1] : 0.f;
            float w2 = (c2 < SUBN) ? Wsub[c2] : 0.f;
            g_cw1[tid] = (c1 < SUBN) ? Cden[tid * SUBN + c1] * w1 * w1 : 0.f;
            g_cw2[tid] = (c2 < SUBN) ? Cden[tid * SUBN + c2] * w2 * w2 : 0.f;
            g_theta[tid] = Theta[tid];
            float wp = Wplex[tid];
            g_wplex2[tid] = wp * wp;
        }
    }

    for (int j = tid; j < nE; j += 256) {
        int sf = 0; float w = 0.f;
#pragma unroll
        for (int s = 0; s < SUBN; s++) {
            float c = Cse[s * nE + j];
            if (c != 0.f) { sf = s; w = c; }
        }
        sidx[j] = sf; sw[j] = w;
    }
    for (int i = tid; i < TT * SUBN; i += 256)
        ((float*)bins)[i] = 0.f;
    __syncthreads();

    int base = blockIdx.x * TT;
    int nrows = min(TT, T - base);
    if (nrows > 0) {
        int nJ4 = nE >> 2;
        const uint4* Se4 = (const uint4*)(Se + (size_t)base * nE);
        int total = nrows * nJ4;
        bool fast = (nJ4 == 125);

        for (int i0 = tid; i0 < total; i0 += 1024) {
            uint4 u0, u1, u2, u3;
            int i1 = i0 + 256, i2 = i0 + 512, i3 = i0 + 768;
            u0 = Se4[i0];
            u1 = (i1 < total) ? Se4[i1] : make_uint4(0, 0, 0, 0);
            u2 = (i2 < total) ? Se4[i2] : make_uint4(0, 0, 0, 0);
            u3 = (i3 < total) ? Se4[i3] : make_uint4(0, 0, 0, 0);
#pragma unroll
            for (int b = 0; b < 4; b++) {
                uint4 u = (b == 0) ? u0 : (b == 1) ? u1 : (b == 2) ? u2 : u3;
                if ((u.x | u.y | u.z | u.w) == 0u) continue;   // ~81% skip
                int idx = i0 + b * 256;
                int tl = fast ? (int)(((unsigned)idx * 33555u) >> 22) : (idx / nJ4);
                int j0 = (idx - tl * nJ4) * 4;
                if (u.x) atomicAdd(&bins[tl][sidx[j0 + 0]], __uint_as_float(u.x) * sw[j0 + 0]);
                if (u.y) atomicAdd(&bins[tl][sidx[j0 + 1]], __uint_as_float(u.y) * sw[j0 + 1]);
                if (u.z) atomicAdd(&bins[tl][sidx[j0 + 2]], __uint_as_float(u.z) * sw[j0 + 2]);
                if (u.w) atomicAdd(&bins[tl][sidx[j0 + 3]], __uint_as_float(u.w) * sw[j0 + 3]);
            }
        }
        __syncthreads();
        for (int i = tid; i < SUBN * TT; i += 256) {
            int s = i >> 7, tl = i & (TT - 1);
            if (tl < nrows)
                g_synT[s * TP + GUARD + base + tl] = bins[tl][s];
        }
    }
}

// ---------------- kernel B: s-major conv (7 outs/lane) + tree + V filter ----
struct ConvSmem {
    float xs[SUBN * XROW];     // 25.9 KB
    float esh[SUBN * KROW];    // 8.3 KB
    float filt[CT * FROW];     // 18.8 KB
    float zsh[CT + KLEN];      // 1.3 KB
    float spk[KLEN];
    float cw1[SUBN], cw2[SUBN], theta[SUBN], wplex2[SUBN];
};

__global__ void __launch_bounds__(CTH, 3) convtree_kernel(const float* __restrict__ Z,
                                                          float* __restrict__ out_V,
                                                          float* __restrict__ out_Z,
                                                          int T)
{
    extern __shared__ __align__(16) char smem_raw[];
    ConvSmem* sm = (ConvSmem*)smem_raw;

    int tid = threadIdx.x;
    int base = blockIdx.x * CT;

    // stage xs: window covers t in [base-100, base+224) = 324 floats/row.
    // word offset GUARD + base - 100 = 28 + base : multiple of 4 -> float4 OK
    for (int i = tid; i < SUBN * (XROW / 4); i += CTH) {
        int s = i / (XROW / 4), q = i % (XROW / 4);
        ((float4*)(sm->xs + s * XROW))[q] =
            ((const float4*)(g_synT + s * TP + 28 + base))[q];
    }
    for (int i = tid; i < SUBN * 26; i += CTH) {
        int s = i / 26, q = i % 26;
        ((float4*)(sm->esh + s * KROW))[q] =
            ((const float4*)(g_ekern2_sj + s * KROW))[q];
    }
    for (int i = tid; i < CT + KLEN; i += CTH) {
        int g = base - KLEN + i;
        sm->zsh[i] = (g >= 0 && g < T) ? Z[g] : 0.f;
    }
    for (int i = tid; i < KLEN; i += CTH) sm->spk[i] = g_spk[i];
    if (tid < SUBN) {
        sm->cw1[tid] = g_cw1[tid]; sm->cw2[tid] = g_cw2[tid];
        sm->theta[tid] = g_theta[tid]; sm->wplex2[tid] = g_wplex2[tid];
    }
    __syncthreads();

    // ---- conv phase: warp w = subunit s; lane owns 7 contiguous outputs ----
    {
        int w = tid >> 5, l = tid & 31;
        const float* xrow = sm->xs + w * XROW;
        const float* krow = sm->esh + w * KROW;
        int p0 = 100 + l * OPL;               // stride 7: conflict-free
        float wbuf[OPL], acc[OPL];
#pragma unroll
        for (int k = 0; k < OPL; k++) {
            wbuf[k] = xrow[p0 + k];
            acc[k] = 0.f;
        }
#pragma unroll 10
        for (int j = 0; j < KLEN; j++) {
            float kj = krow[j];               // broadcast
#pragma unroll
            for (int k = 0; k < OPL; k++)
                acc[k] = fmaf(kj, wbuf[k], acc[k]);
#pragma unroll
            for (int k = OPL - 1; k > 0; k--) // rolling window (renamed regs)
                wbuf[k] = wbuf[k - 1];
            wbuf[0] = xrow[p0 - j - 1];
        }
        int t0 = l * OPL;
#pragma unroll
        for (int k = 0; k < OPL; k++)         // lane stride 147%32=19: cf-free
            sm->filt[(t0 + k) * FROW + w] = acc[k];
    }
    __syncthreads();

    // ---- phase 2: tree (threads 0..223) + V filter (threads 224..447) ----
    if (tid < CT) {
        int t = base + tid;
        if (t < T) {
            const float* f = sm->filt + tid * FROW;
            float sub[SUBN];
#pragma unroll
            for (int s = SUBN - 1; s >= 0; s--) {
                float anc = 0.f;
                if (2 * s + 1 < SUBN) anc = fmaf(sm->cw1[s], sub[2 * s + 1], anc);
                if (2 * s + 2 < SUBN) anc = fmaf(sm->cw2[s], sub[2 * s + 2], anc);
                float x = f[s] + sm->theta[s] + anc;
                sub[s] = tanh_fast(x) * sm->wplex2[s];
            }
            out_Z[t] = 1.f / (1.f + __expf(-sub[0]));
        }
    } else if (tid < 2 * CT) {
        int o = tid - CT;
        int t = base + o;
        if (t < T) {
            float v = 0.f;
#pragma unroll 4
            for (int j = 0; j < KLEN; j++)
                v = fmaf(sm->spk[j], sm->zsh[o + (KLEN - 1) - j], v);
            out_V[t] = v;
        }
    }
}

// ---------------- launch ----------------
extern "C" void kernel_launch(void* const* d_in, const int* in_sizes, int n_in,
                              void* d_out, int out_size)
{
    // 0:S_e 1:S_i 2:Z 3:C_den 4:C_syn_e 5:C_syn_i 6:W_syn 7:Tau_syn 8:Delta_syn
    // 9:W_plex 10:W_sub 11:W_spk 12:Tau_spk 13:Theta 14:T_no
    const float* Se    = (const float*)d_in[0];
    const float* Z     = (const float*)d_in[2];
    const float* Cden  = (const float*)d_in[3];
    const float* Cse   = (const float*)d_in[4];
    const float* Wsyn  = (const float*)d_in[6];
    const float* Tausyn= (const float*)d_in[7];
    const float* Dsyn  = (const float*)d_in[8];
    const float* Wplex = (const float*)d_in[9];
    const float* Wsub  = (const float*)d_in[10];
    const float* Wspk  = (const float*)d_in[11];
    const float* Tauspk= (const float*)d_in[12];
    const float* Theta = (const float*)d_in[13];

    int T  = in_sizes[2];
    int nE = in_sizes[4] / SUBN;
    if (T > T_MAX) T = T_MAX;
    if (nE > NE_MAX) nE = NE_MAX;

    float* out = (float*)d_out;
    float* out_V = out;                   // [T]
    float* out_Z = out + T;               // [T]
    float* out_F = out + 2 * (size_t)T;   // [40, 100]

    static bool attr_set = false;
    if (!attr_set) {
        cudaFuncSetAttribute(convtree_kernel,
                             cudaFuncAttributeMaxDynamicSharedMemorySize,
                             (int)sizeof(ConvSmem));
        attr_set = true;
    }

    int ablocks = (T + TT - 1) / TT;
    synE_kernel<<<ablocks, 256>>>(Se, Cse, Wsyn, Tausyn, Dsyn, Wplex, Wsub,
                                  Wspk, Tauspk, Theta, Cden, out_F, T, nE);
    int bblocks = (T + CT - 1) / CT;
    convtree_kernel<<<bblocks, CTH, sizeof(ConvSmem)>>>(Z, out_V, out_Z, T);
}

// round 17
// speedup vs baseline: 1.0223x; 1.0223x over previous
#include <cuda_runtime.h>
#include <cuda_bf16.h>
#include <math.h>

#define SUBN 20
#define KLEN 100
#define NE_MAX 500
#define T_MAX 100000

#define TT 128                // timesteps per synE block
#define GUARD 128
#define TP (T_MAX + 2*GUARD)  // g_synT row stride (100256)
#define CT 160                // conv tile timesteps
#define CTH 640               // conv threads = 20 warps
#define XROW 264              // xs smem row stride (260 used)
#define KROW 104              // kernel smem row stride
#define FROW 21               // filt smem row stride (odd -> conflict-free)

// ---------------- device scratch (zero-initialized; guards never written) ----
__device__ __align__(16) float g_synT[SUBN * TP];        // [s][t] + guard bands
__device__ __align__(16) float g_ekern2_sj[SUBN * KROW]; // 2*e_kern, [s][j]
__device__ float g_cw1[SUBN], g_cw2[SUBN];
__device__ float g_theta[SUBN], g_wplex2[SUBN];
__device__ float g_spk[KLEN];

__device__ __forceinline__ float tanh_fast(float x) {
    float y;
    asm("tanh.approx.f32 %0, %1;" : "=f"(y) : "f"(x));
    return y;
}

// ---------------- kernel A: prep (block 0) + syn_e scatter (transposed out) --
__global__ void __launch_bounds__(256) synE_kernel(
    const float* __restrict__ Se, const float* __restrict__ Cse,
    const float* __restrict__ Wsyn, const float* __restrict__ Tausyn,
    const float* __restrict__ Dsyn, const float* __restrict__ Wplex,
    const float* __restrict__ Wsub, const float* __restrict__ Wspk,
    const float* __restrict__ Tauspk, const float* __restrict__ Theta,
    const float* __restrict__ Cden, float* __restrict__ out_filters,
    int T, int nE)
{
    __shared__ float bins[TT][SUBN];
    __shared__ int   sidx[NE_MAX];
    __shared__ float sw[NE_MAX];
    int tid = threadIdx.x;

    if (blockIdx.x == 0) {
        for (int i = tid; i < SUBN * KLEN; i += 256) {
            int s = i / KLEN, k = i % KLEN;
            float te = fmaxf((float)k - Dsyn[s * 2 + 0], 0.f);
            float ti = fmaxf((float)k - Dsyn[s * 2 + 1], 0.f);
            float taue = Tausyn[s * 2 + 0];
            float taui = Tausyn[s * 2 + 1];
            float tte = te / (taue * taue);
            float tti = ti / (taui * taui);
            float ek = tte * expf(-tte) * Wsyn[s * 2 + 0];
            float ik = tti * expf(-tti) * Wsyn[s * 2 + 1];
            out_filters[s * KLEN + k] = ek;
            out_filters[(SUBN + s) * KLEN + k] = ik;
            g_ekern2_sj[s * KROW + k] = 2.f * ek;   // fold filt_e + filt_e
        }
        for (int i = tid; i < KLEN; i += 256) {
            float ts = Tauspk[0];
            float tt = (float)i / (ts * ts);
            g_spk[i] = tt * expf(-tt) * Wspk[0] * Wspk[0];
        }
        if (tid < SUBN) {
            int c1 = 2 * tid + 1, c2 = 2 * tid + 2;   // binary dendritic tree
            float w1 = (c1 < SUBN) ? Wsub[c1] : 0.f;
            float w2 = (c2 < SUBN) ? Wsub[c2] : 0.f;
            g_cw1[tid] = (c1 < SUBN) ? Cden[tid * SUBN + c1] * w1 * w1 : 0.f;
            g_cw2[tid] = (c2 < SUBN) ? Cden[tid * SUBN + c2] * w2 * w2 : 0.f;
            g_theta[tid] = Theta[tid];
            float wp = Wplex[tid];
            g_wplex2[tid] = wp * wp;
        }
    }

    for (int j = tid; j < nE; j += 256) {
        int sf = 0; float w = 0.f;
#pragma unroll
        for (int s = 0; s < SUBN; s++) {
            float c = Cse[s * nE + j];
            if (c != 0.f) { sf = s; w = c; }
        }
        sidx[j] = sf; sw[j] = w;
    }
    for (int i = tid; i < TT * SUBN; i += 256)
        ((float*)bins)[i] = 0.f;
    __syncthreads();

    int base = blockIdx.x * TT;
    int nrows = min(TT, T - base);
    if (nrows > 0) {
        int nJ4 = nE >> 2;
        const uint4* Se4 = (const uint4*)(Se + (size_t)base * nE);
        int total = nrows * nJ4;
        bool fast = (nJ4 == 125);

        for (int i0 = tid; i0 < total; i0 += 1024) {
            uint4 u0, u1, u2, u3;
            int i1 = i0 + 256, i2 = i0 + 512, i3 = i0 + 768;
            u0 = Se4[i0];
            u1 = (i1 < total) ? Se4[i1] : make_uint4(0, 0, 0, 0);
            u2 = (i2 < total) ? Se4[i2] : make_uint4(0, 0, 0, 0);
            u3 = (i3 < total) ? Se4[i3] : make_uint4(0, 0, 0, 0);
#pragma unroll
            for (int b = 0; b < 4; b++) {
                uint4 u = (b == 0) ? u0 : (b == 1) ? u1 : (b == 2) ? u2 : u3;
                if ((u.x | u.y | u.z | u.w) == 0u) continue;   // ~81% skip
                int idx = i0 + b * 256;
                int tl = fast ? (int)(((unsigned)idx * 33555u) >> 22) : (idx / nJ4);
                int j0 = (idx - tl * nJ4) * 4;
                if (u.x) atomicAdd(&bins[tl][sidx[j0 + 0]], __uint_as_float(u.x) * sw[j0 + 0]);
                if (u.y) atomicAdd(&bins[tl][sidx[j0 + 1]], __uint_as_float(u.y) * sw[j0 + 1]);
                if (u.z) atomicAdd(&bins[tl][sidx[j0 + 2]], __uint_as_float(u.z) * sw[j0 + 2]);
                if (u.w) atomicAdd(&bins[tl][sidx[j0 + 3]], __uint_as_float(u.w) * sw[j0 + 3]);
            }
        }
        __syncthreads();
        for (int i = tid; i < SUBN * TT; i += 256) {
            int s = i >> 7, tl = i & (TT - 1);
            if (tl < nrows)
                g_synT[s * TP + GUARD + base + tl] = bins[tl][s];
        }
    }
}

// ---------------- kernel B: s-major conv + tree + sigmoid + V filter --------
// measured-best configuration: esh in smem, 5 outputs/lane,
// __launch_bounds__(640, 3) -> regs 32, 3 blocks/SM.
__global__ void __launch_bounds__(CTH, 3) convtree_kernel(const float* __restrict__ Z,
                                                          float* __restrict__ out_V,
                                                          float* __restrict__ out_Z,
                                                          int T)
{
    __shared__ __align__(16) float xs[SUBN * XROW];    // [s][260] window, 21.1 KB
    __shared__ __align__(16) float esh[SUBN * KROW];   // [s][100], 8.3 KB
    __shared__ float filt[CT * FROW];                  // [t][21], 13.4 KB
    __shared__ float zsh[CT + KLEN];
    __shared__ float spk[KLEN];
    __shared__ float cw1[SUBN], cw2[SUBN], theta[SUBN], wplex2[SUBN];

    int tid = threadIdx.x;
    int base = blockIdx.x * CT;

    // stage xs: rows cover global t in [base-100, base+160); guards give zeros
    // word offset GUARD + base - 100 = 28 + base : multiple of 4 -> float4 OK
    for (int i = tid; i < SUBN * 65; i += CTH) {
        int s = i / 65, q = i % 65;
        ((float4*)(xs + s * XROW))[q] =
            ((const float4*)(g_synT + s * TP + 28 + base))[q];
    }
    for (int i = tid; i < SUBN * 26; i += CTH) {
        int s = i / 26, q = i % 26;
        ((float4*)(esh + s * KROW))[q] =
            ((const float4*)(g_ekern2_sj + s * KROW))[q];
    }
    for (int i = tid; i < CT + KLEN; i += CTH) {
        int g = base - KLEN + i;
        zsh[i] = (g >= 0 && g < T) ? Z[g] : 0.f;
    }
    for (int i = tid; i < KLEN; i += CTH) spk[i] = g_spk[i];
    if (tid < SUBN) {
        cw1[tid] = g_cw1[tid]; cw2[tid] = g_cw2[tid];
        theta[tid] = g_theta[tid]; wplex2[tid] = g_wplex2[tid];
    }
    __syncthreads();

    // ---- conv phase: warp w = subunit s; lane owns 5 contiguous outputs ----
    {
        int w = tid >> 5, l = tid & 31;
        const float* xrow = xs + w * XROW;
        const float* krow = esh + w * KROW;
        int p0 = 100 + l * 5;                 // xs position of first output
        float w0 = xrow[p0 + 0];
        float w1 = xrow[p0 + 1];
        float w2 = xrow[p0 + 2];
        float w3 = xrow[p0 + 3];
        float w4 = xrow[p0 + 4];
        float a0 = 0.f, a1 = 0.f, a2 = 0.f, a3 = 0.f, a4 = 0.f;
#pragma unroll 10
        for (int j = 0; j < KLEN; j++) {
            float kj = krow[j];               // broadcast
            a0 = fmaf(kj, w0, a0);
            a1 = fmaf(kj, w1, a1);
            a2 = fmaf(kj, w2, a2);
            a3 = fmaf(kj, w3, a3);
            a4 = fmaf(kj, w4, a4);
            w4 = w3; w3 = w2; w2 = w1; w1 = w0;   // rolling window
            w0 = xrow[p0 - j - 1];
        }
        int t0 = l * 5;
        filt[(t0 + 0) * FROW + w] = a0;       // stride-105 writes: conflict-free
        filt[(t0 + 1) * FROW + w] = a1;
        filt[(t0 + 2) * FROW + w] = a2;
        filt[(t0 + 3) * FROW + w] = a3;
        filt[(t0 + 4) * FROW + w] = a4;
    }
    __syncthreads();

    // ---- phase 2: tree (threads 0..159) + V filter (threads 160..319) ----
    if (tid < CT) {
        int t = base + tid;
        if (t < T) {
            const float* f = filt + tid * FROW;
            float sub[SUBN];
#pragma unroll
            for (int s = SUBN - 1; s >= 0; s--) {
                float anc = 0.f;
                if (2 * s + 1 < SUBN) anc = fmaf(cw1[s], sub[2 * s + 1], anc);
                if (2 * s + 2 < SUBN) anc = fmaf(cw2[s], sub[2 * s + 2], anc);
                float x = f[s] + theta[s] + anc;
                sub[s] = tanh_fast(x) * wplex2[s];
            }
            out_Z[t] = 1.f / (1.f + __expf(-sub[0]));
        }
    } else if (tid < 2 * CT) {
        int o = tid - CT;
        int t = base + o;
        if (t < T) {
            float v = 0.f;
#pragma unroll 4
            for (int j = 0; j < KLEN; j++)
                v = fmaf(spk[j], zsh[o + (KLEN - 1) - j], v);
            out_V[t] = v;
        }
    }
}

// ---------------- launch ----------------
extern "C" void kernel_launch(void* const* d_in, const int* in_sizes, int n_in,
                              void* d_out, int out_size)
{
    // 0:S_e 1:S_i 2:Z 3:C_den 4:C_syn_e 5:C_syn_i 6:W_syn 7:Tau_syn 8:Delta_syn
    // 9:W_plex 10:W_sub 11:W_spk 12:Tau_spk 13:Theta 14:T_no
    const float* Se    = (const float*)d_in[0];
    const float* Z     = (const float*)d_in[2];
    const float* Cden  = (const float*)d_in[3];
    const float* Cse   = (const float*)d_in[4];
    const float* Wsyn  = (const float*)d_in[6];
    const float* Tausyn= (const float*)d_in[7];
    const float* Dsyn  = (const float*)d_in[8];
    const float* Wplex = (const float*)d_in[9];
    const float* Wsub  = (const float*)d_in[10];
    const float* Wspk  = (const float*)d_in[11];
    const float* Tauspk= (const float*)d_in[12];
    const float* Theta = (const float*)d_in[13];

    int T  = in_sizes[2];
    int nE = in_sizes[4] / SUBN;
    if (T > T_MAX) T = T_MAX;
    if (nE > NE_MAX) nE = NE_MAX;

    float* out = (float*)d_out;
    float* out_V = out;                   // [T]
    float* out_Z = out + T;               // [T]
    float* out_F = out + 2 * (size_t)T;   // [40, 100]

    int ablocks = (T + TT - 1) / TT;
    synE_kernel<<<ablocks, 256>>>(Se, Cse, Wsyn, Tausyn, Dsyn, Wplex, Wsub,
                                  Wspk, Tauspk, Theta, Cden, out_F, T, nE);
    int bblocks = (T + CT - 1) / CT;
    convtree_kernel<<<bblocks, CTH>>>(Z, out_V, out_Z, T);
}